// round 2
// baseline (speedup 1.0000x reference)
#include <cuda_runtime.h>

#define BATCH  2
#define SEQ    2048
#define HEADS  12
#define DHEAD  64
#define DMODEL 768
#define NQKV   2304          // 3 * DMODEL
#define MTOK   (BATCH * SEQ) // 4096

// ---------------- scratch (static device globals: no allocation allowed) ----
__device__ float g_Wqkv[(size_t)DMODEL * NQKV];   // repacked [768, 2304]
__device__ float g_bqkv[NQKV];
__device__ float g_qkv[(size_t)MTOK * NQKV];      // [4096, 2304] : q|k|v
__device__ float g_z[(size_t)MTOK * DMODEL];      // [4096, 768]  : attn out

// ---------------- repack W_Q/W_K/W_V -> [dm, h*64+k] columns ----------------
__global__ void repack_kernel(const float* __restrict__ WQ,
                              const float* __restrict__ WK,
                              const float* __restrict__ WV,
                              const float* __restrict__ bQ,
                              const float* __restrict__ bK,
                              const float* __restrict__ bV) {
    int idx = blockIdx.x * blockDim.x + threadIdx.x;
    if (idx < DMODEL * DMODEL) {
        int dm = idx / DMODEL;
        int c  = idx % DMODEL;          // c = h*64 + k
        int h  = c >> 6, k = c & 63;
        size_t src = ((size_t)h * DMODEL + dm) * DHEAD + k;
        size_t dst = (size_t)dm * NQKV + c;
        g_Wqkv[dst]              = WQ[src];
        g_Wqkv[dst + DMODEL]     = WK[src];
        g_Wqkv[dst + 2 * DMODEL] = WV[src];
    }
    if (idx < DMODEL) {
        g_bqkv[idx]              = bQ[idx];
        g_bqkv[idx + DMODEL]     = bK[idx];
        g_bqkv[idx + 2 * DMODEL] = bV[idx];
    }
}

// ---------------- SGEMM: C[M,N] = A[M,K] @ B[K,N] + bias[N] ----------------
// 128x128 block tile, BK=8, 256 threads, 8x8 per-thread micro tile.
#define BM 128
#define BN 128
#define BK 8
#define TM 8
#define TN 8

__global__ __launch_bounds__(256)
void sgemm_kernel(int M, int N, int K,
                  const float* __restrict__ A,
                  const float* __restrict__ B,
                  const float* __restrict__ bias,
                  float* __restrict__ C) {
    __shared__ float As[BK][BM];
    __shared__ float Bs[BK][BN];

    const int tid  = threadIdx.x;
    const int brow = blockIdx.y * BM;
    const int bcol = blockIdx.x * BN;

    const int trow = (tid / (BN / TN)) * TM;  // 0..120 step 8
    const int tcol = (tid % (BN / TN)) * TN;

    // global->shared mapping (vectorized float4)
    const int arow = tid >> 1;            // 128 rows
    const int acol = (tid & 1) * 4;       // 8 cols, 2 float4 per row
    const int brw  = tid >> 5;            // 8 rows
    const int bcl  = (tid & 31) * 4;      // 128 cols

    float acc[TM][TN] = {};

    for (int k0 = 0; k0 < K; k0 += BK) {
        float4 a4 = *(const float4*)&A[(size_t)(brow + arow) * K + k0 + acol];
        As[acol + 0][arow] = a4.x;
        As[acol + 1][arow] = a4.y;
        As[acol + 2][arow] = a4.z;
        As[acol + 3][arow] = a4.w;
        float4 b4 = *(const float4*)&B[(size_t)(k0 + brw) * N + bcol + bcl];
        *(float4*)&Bs[brw][bcl] = b4;
        __syncthreads();

#pragma unroll
        for (int k = 0; k < BK; k++) {
            float ar[TM], br[TN];
#pragma unroll
            for (int i = 0; i < TM; i++) ar[i] = As[k][trow + i];
#pragma unroll
            for (int j = 0; j < TN; j++) br[j] = Bs[k][tcol + j];
#pragma unroll
            for (int i = 0; i < TM; i++)
#pragma unroll
                for (int j = 0; j < TN; j++)
                    acc[i][j] = fmaf(ar[i], br[j], acc[i][j]);
        }
        __syncthreads();
    }

#pragma unroll
    for (int i = 0; i < TM; i++) {
#pragma unroll
        for (int j = 0; j < TN; j += 4) {
            float4 v;
            v.x = acc[i][j + 0] + bias[bcol + tcol + j + 0];
            v.y = acc[i][j + 1] + bias[bcol + tcol + j + 1];
            v.z = acc[i][j + 2] + bias[bcol + tcol + j + 2];
            v.w = acc[i][j + 3] + bias[bcol + tcol + j + 3];
            *(float4*)&C[(size_t)(brow + trow + i) * N + bcol + tcol + j] = v;
        }
    }
}

// ---------------- causal flash attention --------------------------------
// grid (SEQ/64, HEADS, BATCH), 256 threads. 64-row Q tile, 64-key KV tiles.
// Each thread: 4 q-rows x 4 cols (16x16 thread grid). Online softmax.
#define PAD 65
#define SMEM_ATTN (4 * 64 * PAD * (int)sizeof(float))   // Qs,Ks,Vs,Ps

__global__ __launch_bounds__(256)
void attn_kernel() {
    extern __shared__ float sm[];
    float* Qs = sm;                 // [64][65]
    float* Ks = sm + 64 * PAD;
    float* Vs = sm + 2 * 64 * PAD;
    float* Ps = sm + 3 * 64 * PAD;

    const int qb  = blockIdx.x;
    const int h   = blockIdx.y;
    const int b   = blockIdx.z;
    const int tid = threadIdx.x;
    const int tx  = tid & 15, ty = tid >> 4;
    const int r0  = ty * 4, c0 = tx * 4;

    // load Q tile
    for (int i = tid; i < 64 * 16; i += 256) {
        int r = i >> 4, c = (i & 15) * 4;
        float4 v = *(const float4*)&g_qkv[((size_t)(b * SEQ + qb * 64 + r)) * NQKV + h * DHEAD + c];
        Qs[r * PAD + c + 0] = v.x; Qs[r * PAD + c + 1] = v.y;
        Qs[r * PAD + c + 2] = v.z; Qs[r * PAD + c + 3] = v.w;
    }

    float o[4][4] = {};
    float m[4] = {-1e30f, -1e30f, -1e30f, -1e30f};
    float l[4] = {};

    for (int j = 0; j <= qb; j++) {
        __syncthreads();  // previous Ps/Vs consumers done before overwrite
        for (int i = tid; i < 64 * 16; i += 256) {
            int r = i >> 4, c = (i & 15) * 4;
            size_t base = ((size_t)(b * SEQ + j * 64 + r)) * NQKV + h * DHEAD + c;
            float4 kv = *(const float4*)&g_qkv[base + DMODEL];
            Ks[r * PAD + c + 0] = kv.x; Ks[r * PAD + c + 1] = kv.y;
            Ks[r * PAD + c + 2] = kv.z; Ks[r * PAD + c + 3] = kv.w;
            float4 vv = *(const float4*)&g_qkv[base + 2 * DMODEL];
            Vs[r * PAD + c + 0] = vv.x; Vs[r * PAD + c + 1] = vv.y;
            Vs[r * PAD + c + 2] = vv.z; Vs[r * PAD + c + 3] = vv.w;
        }
        __syncthreads();

        // S = Q @ K^T (4x4 micro tile)
        float s[4][4] = {};
#pragma unroll 8
        for (int d = 0; d < 64; d++) {
            float qr[4], kc[4];
#pragma unroll
            for (int i = 0; i < 4; i++) qr[i] = Qs[(r0 + i) * PAD + d];
#pragma unroll
            for (int jj = 0; jj < 4; jj++) kc[jj] = Ks[(c0 + jj) * PAD + d];
#pragma unroll
            for (int i = 0; i < 4; i++)
#pragma unroll
                for (int jj = 0; jj < 4; jj++)
                    s[i][jj] = fmaf(qr[i], kc[jj], s[i][jj]);
        }

        const bool diag = (j == qb);
#pragma unroll
        for (int i = 0; i < 4; i++) {
            float mx = -1e30f;
#pragma unroll
            for (int jj = 0; jj < 4; jj++) {
                float v = s[i][jj] * 0.125f;   // 1/sqrt(64)
                if (diag && (c0 + jj) > (r0 + i)) v = -1e30f;
                s[i][jj] = v;
                mx = fmaxf(mx, v);
            }
            // row max across 16 threads (same half-warp group)
#pragma unroll
            for (int off = 8; off; off >>= 1)
                mx = fmaxf(mx, __shfl_xor_sync(0xffffffffu, mx, off));
            float mnew  = fmaxf(m[i], mx);
            float alpha = __expf(m[i] - mnew);
            m[i] = mnew;
            float rs = 0.f;
#pragma unroll
            for (int jj = 0; jj < 4; jj++) {
                float p = __expf(s[i][jj] - mnew);
                Ps[(r0 + i) * PAD + c0 + jj] = p;
                rs += p;
            }
#pragma unroll
            for (int off = 8; off; off >>= 1)
                rs += __shfl_xor_sync(0xffffffffu, rs, off);
            l[i] = l[i] * alpha + rs;
#pragma unroll
            for (int jj = 0; jj < 4; jj++) o[i][jj] *= alpha;
        }
        __syncthreads();  // Ps visible

        // O += P @ V
#pragma unroll 8
        for (int k = 0; k < 64; k++) {
            float pr[4], vc[4];
#pragma unroll
            for (int i = 0; i < 4; i++) pr[i] = Ps[(r0 + i) * PAD + k];
#pragma unroll
            for (int jj = 0; jj < 4; jj++) vc[jj] = Vs[k * PAD + c0 + jj];
#pragma unroll
            for (int i = 0; i < 4; i++)
#pragma unroll
                for (int jj = 0; jj < 4; jj++)
                    o[i][jj] = fmaf(pr[i], vc[jj], o[i][jj]);
        }
    }

    // epilogue: divide by l, write z [B,S,H,DHEAD] == [4096,768]
#pragma unroll
    for (int i = 0; i < 4; i++) {
        float inv = 1.0f / l[i];
        float4 v;
        v.x = o[i][0] * inv; v.y = o[i][1] * inv;
        v.z = o[i][2] * inv; v.w = o[i][3] * inv;
        *(float4*)&g_z[((size_t)(b * SEQ + qb * 64 + r0 + i)) * DMODEL + h * DHEAD + c0] = v;
    }
}

// ---------------- launch -------------------------------------------------
extern "C" void kernel_launch(void* const* d_in, const int* in_sizes, int n_in,
                              void* d_out, int out_size) {
    const float* x  = (const float*)d_in[0];
    const float* WQ = (const float*)d_in[1];
    const float* WK = (const float*)d_in[2];
    const float* WV = (const float*)d_in[3];
    const float* bQ = (const float*)d_in[4];
    const float* bK = (const float*)d_in[5];
    const float* bV = (const float*)d_in[6];
    const float* WO = (const float*)d_in[7];
    const float* bO = (const float*)d_in[8];
    float* out = (float*)d_out;

    float *pWqkv, *pbqkv, *pqkv, *pz;
    cudaGetSymbolAddress((void**)&pWqkv, g_Wqkv);
    cudaGetSymbolAddress((void**)&pbqkv, g_bqkv);
    cudaGetSymbolAddress((void**)&pqkv,  g_qkv);
    cudaGetSymbolAddress((void**)&pz,    g_z);

    // 1) repack weights + biases
    repack_kernel<<<(DMODEL * DMODEL + 255) / 256, 256>>>(WQ, WK, WV, bQ, bK, bV);

    // 2) fused QKV projection: [4096,768] @ [768,2304] + bias
    sgemm_kernel<<<dim3(NQKV / BN, MTOK / BM), 256>>>(MTOK, NQKV, DMODEL, x, pWqkv, pbqkv, pqkv);

    // 3) causal flash attention
    cudaFuncSetAttribute(attn_kernel, cudaFuncAttributeMaxDynamicSharedMemorySize, SMEM_ATTN);
    attn_kernel<<<dim3(SEQ / 64, HEADS, BATCH), 256, SMEM_ATTN>>>();

    // 4) output projection: [4096,768] @ [768,768] + b_O  (W_O already [768,768])
    sgemm_kernel<<<dim3(DMODEL / BN, MTOK / BM), 256>>>(MTOK, DMODEL, DMODEL, pz, WO, bO, out);
}

// round 5
// speedup vs baseline: 1.3100x; 1.3100x over previous
#include <cuda_runtime.h>
#include <cuda_bf16.h>

#define BATCH  2
#define SEQ    2048
#define HEADS  12
#define DHEAD  64
#define DMODEL 768
#define NQKV   2304
#define MTOK   4096
#define KDIM   768

// ---------------- device scratch -------------------------------------------
__device__ __align__(16) __nv_bfloat16 g_xhi[(size_t)MTOK * KDIM];
__device__ __align__(16) __nv_bfloat16 g_xlo[(size_t)MTOK * KDIM];
__device__ __align__(16) __nv_bfloat16 g_Wthi[(size_t)NQKV * KDIM];  // [n][k]
__device__ __align__(16) __nv_bfloat16 g_Wtlo[(size_t)NQKV * KDIM];
__device__ __align__(16) __nv_bfloat16 g_Wohi[(size_t)DMODEL * KDIM];
__device__ __align__(16) __nv_bfloat16 g_Wolo[(size_t)DMODEL * KDIM];
__device__ __align__(16) __nv_bfloat16 g_zhi[(size_t)MTOK * KDIM];
__device__ __align__(16) __nv_bfloat16 g_zlo[(size_t)MTOK * KDIM];
__device__ float g_bqkv[NQKV];
__device__ __align__(16) float g_qkv[(size_t)MTOK * NQKV];
__device__ __align__(16) float g_z[(size_t)MTOK * DMODEL];

__device__ __forceinline__ void split2(float v, __nv_bfloat16& h, __nv_bfloat16& l) {
    h = __float2bfloat16(v);
    l = __float2bfloat16(v - __bfloat162float(h));
}
__device__ __forceinline__ unsigned smem_u32(const void* p) {
    unsigned a;
    asm("{ .reg .u64 t; cvta.to.shared.u64 t, %1; cvt.u32.u64 %0, t; }" : "=r"(a) : "l"(p));
    return a;
}

// ---------------- weight repack + bf16 split --------------------------------
__global__ void prep_weights(const float* __restrict__ WQ, const float* __restrict__ WK,
                             const float* __restrict__ WV, const float* __restrict__ bQ,
                             const float* __restrict__ bK, const float* __restrict__ bV,
                             const float* __restrict__ WO) {
    int idx = blockIdx.x * blockDim.x + threadIdx.x;
    if (idx >= DMODEL * DMODEL) return;
    int h = idx / (DMODEL * DHEAD);
    int r = idx % (DMODEL * DHEAD);
    int dm = r / DHEAD, dk = r % DHEAD;
    int n = h * DHEAD + dk;
    __nv_bfloat16 hi, lo;
    split2(WQ[idx], hi, lo);
    g_Wthi[(size_t)n * KDIM + dm] = hi;                 g_Wtlo[(size_t)n * KDIM + dm] = lo;
    split2(WK[idx], hi, lo);
    g_Wthi[(size_t)(n + DMODEL) * KDIM + dm] = hi;      g_Wtlo[(size_t)(n + DMODEL) * KDIM + dm] = lo;
    split2(WV[idx], hi, lo);
    g_Wthi[(size_t)(n + 2 * DMODEL) * KDIM + dm] = hi;  g_Wtlo[(size_t)(n + 2 * DMODEL) * KDIM + dm] = lo;
    int kk = idx / DMODEL, nn = idx % DMODEL;
    split2(WO[idx], hi, lo);
    g_Wohi[(size_t)nn * KDIM + kk] = hi;
    g_Wolo[(size_t)nn * KDIM + kk] = lo;
    if (idx < DMODEL) {
        g_bqkv[idx] = bQ[idx];
        g_bqkv[idx + DMODEL] = bK[idx];
        g_bqkv[idx + 2 * DMODEL] = bV[idx];
    }
}

__global__ void convert_split(const float* __restrict__ src, __nv_bfloat16* __restrict__ hi,
                              __nv_bfloat16* __restrict__ lo, int n) {
    int i = blockIdx.x * blockDim.x + threadIdx.x;
    if (i < n) split2(src[i], hi[i], lo[i]);
}

// ---------------- HMMA GEMM (mma.sync bf16, 3-pass hi/lo split) -------------
// C[M,N] = A[M,768] @ Bt[N,768]^T + bias.  128x128 CTA tile, BK=64,
// cp.async double buffer, 8 warps (64x32 warp tile), m16n8k16.
#define BK      64
#define LDS_PAD 8
#define LDS_STR (BK + LDS_PAD)              // 72 bf16 = 144 B row stride
#define STAGE_B (2 * 128 * LDS_STR * 2)     // A(18432) + B(18432) bytes
#define GSMEM   (2 * STAGE_B)               // 73728 B

__device__ __forceinline__ void cp16(unsigned saddr, const void* gaddr) {
    asm volatile("cp.async.cg.shared.global [%0], [%1], 16;" :: "r"(saddr), "l"(gaddr));
}
__device__ __forceinline__ void cp_commit() { asm volatile("cp.async.commit_group;"); }
template <int N>
__device__ __forceinline__ void cp_wait() { asm volatile("cp.async.wait_group %0;" :: "n"(N)); }

__device__ __forceinline__ void ldsm_x4(unsigned addr, unsigned& r0, unsigned& r1,
                                        unsigned& r2, unsigned& r3) {
    asm volatile("ldmatrix.sync.aligned.m8n8.x4.shared.b16 {%0,%1,%2,%3}, [%4];"
                 : "=r"(r0), "=r"(r1), "=r"(r2), "=r"(r3) : "r"(addr));
}
__device__ __forceinline__ void ldsm_x2(unsigned addr, unsigned& r0, unsigned& r1) {
    asm volatile("ldmatrix.sync.aligned.m8n8.x2.shared.b16 {%0,%1}, [%2];"
                 : "=r"(r0), "=r"(r1) : "r"(addr));
}
__device__ __forceinline__ void mma_bf16(float* d, const unsigned* a, const unsigned* b) {
    asm volatile("mma.sync.aligned.m16n8k16.row.col.f32.bf16.bf16.f32 "
                 "{%0,%1,%2,%3}, {%4,%5,%6,%7}, {%8,%9}, {%0,%1,%2,%3};"
                 : "+f"(d[0]), "+f"(d[1]), "+f"(d[2]), "+f"(d[3])
                 : "r"(a[0]), "r"(a[1]), "r"(a[2]), "r"(a[3]), "r"(b[0]), "r"(b[1]));
}

// load one 128x64 bf16 tile into padded smem (16B cp.async per op)
__device__ __forceinline__ void load_stage(unsigned sA, unsigned sB,
                                           const __nv_bfloat16* __restrict__ A,
                                           const __nv_bfloat16* __restrict__ B,
                                           int arow0, int brow0, int k0, int tid) {
#pragma unroll
    for (int t = 0; t < 4; t++) {
        int i = tid + t * 256;                 // 0..1023
        int row = i >> 3, seg = i & 7;         // seg*8 bf16 = 16B
        cp16(sA + row * (LDS_STR * 2) + seg * 16,
             A + (size_t)(arow0 + row) * KDIM + k0 + seg * 8);
        cp16(sB + row * (LDS_STR * 2) + seg * 16,
             B + (size_t)(brow0 + row) * KDIM + k0 + seg * 8);
    }
    cp_commit();
}

__global__ __launch_bounds__(256, 2)
void gemm_hmma(const __nv_bfloat16* __restrict__ Ahi, const __nv_bfloat16* __restrict__ Alo,
               const __nv_bfloat16* __restrict__ Bhi, const __nv_bfloat16* __restrict__ Blo,
               const float* __restrict__ bias, float* __restrict__ C, int Nglob) {
    extern __shared__ char smem[];
    const unsigned sb = smem_u32(smem);
    const int tid = threadIdx.x, wid = tid >> 5, lane = tid & 31;
    const int brow = blockIdx.y * 128, bcol = blockIdx.x * 128;
    const int wm = (wid & 1) * 64, wn = (wid >> 1) * 32;

    const __nv_bfloat16* Aps[3] = {Ahi, Ahi, Alo};
    const __nv_bfloat16* Bps[3] = {Bhi, Blo, Bhi};

    const int NSTAGE = 3 * (KDIM / BK);      // 36
    float acc[4][4][4] = {};

    // ldmatrix source addresses (per-thread, fixed within a buffer)
    const int a_r = lane & 15, a_h = lane >> 4;       // A: row, col-half
    const int b_r = lane & 7,  b_h = (lane >> 3) & 1; // B: row, col-half

    // prologue
    load_stage(sb, sb + 128 * LDS_STR * 2, Aps[0], Bps[0], brow, bcol, 0, tid);

    for (int s = 0; s < NSTAGE; s++) {
        const int buf = s & 1;
        if (s + 1 < NSTAGE) {
            const int p = (s + 1) / (KDIM / BK), k0 = ((s + 1) % (KDIM / BK)) * BK;
            const unsigned off = (1 - buf) * STAGE_B;
            load_stage(sb + off, sb + off + 128 * LDS_STR * 2, Aps[p], Bps[p],
                       brow, bcol, k0, tid);
            cp_wait<1>();
        } else {
            cp_wait<0>();
        }
        __syncthreads();

        const unsigned sA = sb + buf * STAGE_B;
        const unsigned sB = sA + 128 * LDS_STR * 2;
#pragma unroll
        for (int kk = 0; kk < BK; kk += 16) {
            unsigned a[4][4], b[4][2];
#pragma unroll
            for (int mf = 0; mf < 4; mf++)
                ldsm_x4(sA + (wm + mf * 16 + a_r) * (LDS_STR * 2) + (kk + a_h * 8) * 2,
                        a[mf][0], a[mf][1], a[mf][2], a[mf][3]);
#pragma unroll
            for (int nf = 0; nf < 4; nf++)
                ldsm_x2(sB + (wn + nf * 8 + b_r) * (LDS_STR * 2) + (kk + b_h * 8) * 2,
                        b[nf][0], b[nf][1]);
#pragma unroll
            for (int mf = 0; mf < 4; mf++)
#pragma unroll
                for (int nf = 0; nf < 4; nf++)
                    mma_bf16(acc[mf][nf], a[mf], b[nf]);
        }
        __syncthreads();
    }

    // epilogue: acc layout per mma: c0,c1 -> (group, tig*2+{0,1}); c2,c3 -> row+8
    const int grp = lane >> 2, tig = lane & 3;
#pragma unroll
    for (int mf = 0; mf < 4; mf++) {
#pragma unroll
        for (int nf = 0; nf < 4; nf++) {
            const int r1 = brow + wm + mf * 16 + grp;
            const int cc = bcol + wn + nf * 8 + tig * 2;
            float2 v0, v1;
            v0.x = acc[mf][nf][0] + bias[cc];
            v0.y = acc[mf][nf][1] + bias[cc + 1];
            v1.x = acc[mf][nf][2] + bias[cc];
            v1.y = acc[mf][nf][3] + bias[cc + 1];
            *(float2*)&C[(size_t)r1 * Nglob + cc] = v0;
            *(float2*)&C[(size_t)(r1 + 8) * Nglob + cc] = v1;
        }
    }
}

// ---------------- causal flash attention (fp32 SIMT) ------------------------
#define PAD 65
#define SMEM_ATTN (4 * 64 * PAD * (int)sizeof(float))

__global__ __launch_bounds__(256)
void attn_kernel() {
    extern __shared__ float sm[];
    float* Qs = sm;
    float* Ks = sm + 64 * PAD;
    float* Vs = sm + 2 * 64 * PAD;
    float* Ps = sm + 3 * 64 * PAD;

    const int qb  = blockIdx.x;
    const int h   = blockIdx.y;
    const int b   = blockIdx.z;
    const int tid = threadIdx.x;
    const int tx  = tid & 15, ty = tid >> 4;
    const int r0  = ty * 4, c0 = tx * 4;

    for (int i = tid; i < 64 * 16; i += 256) {
        int r = i >> 4, c = (i & 15) * 4;
        float4 v = *(const float4*)&g_qkv[((size_t)(b * SEQ + qb * 64 + r)) * NQKV + h * DHEAD + c];
        Qs[r * PAD + c + 0] = v.x; Qs[r * PAD + c + 1] = v.y;
        Qs[r * PAD + c + 2] = v.z; Qs[r * PAD + c + 3] = v.w;
    }

    float o[4][4] = {};
    float m[4] = {-1e30f, -1e30f, -1e30f, -1e30f};
    float l[4] = {};

    for (int j = 0; j <= qb; j++) {
        __syncthreads();
        for (int i = tid; i < 64 * 16; i += 256) {
            int r = i >> 4, c = (i & 15) * 4;
            size_t base = ((size_t)(b * SEQ + j * 64 + r)) * NQKV + h * DHEAD + c;
            float4 kv = *(const float4*)&g_qkv[base + DMODEL];
            Ks[r * PAD + c + 0] = kv.x; Ks[r * PAD + c + 1] = kv.y;
            Ks[r * PAD + c + 2] = kv.z; Ks[r * PAD + c + 3] = kv.w;
            float4 vv = *(const float4*)&g_qkv[base + 2 * DMODEL];
            Vs[r * PAD + c + 0] = vv.x; Vs[r * PAD + c + 1] = vv.y;
            Vs[r * PAD + c + 2] = vv.z; Vs[r * PAD + c + 3] = vv.w;
        }
        __syncthreads();

        float s[4][4] = {};
#pragma unroll 8
        for (int d = 0; d < 64; d++) {
            float qr[4], kc[4];
#pragma unroll
            for (int i = 0; i < 4; i++) qr[i] = Qs[(r0 + i) * PAD + d];
#pragma unroll
            for (int jj = 0; jj < 4; jj++) kc[jj] = Ks[(c0 + jj) * PAD + d];
#pragma unroll
            for (int i = 0; i < 4; i++)
#pragma unroll
                for (int jj = 0; jj < 4; jj++)
                    s[i][jj] = fmaf(qr[i], kc[jj], s[i][jj]);
        }

        const bool diag = (j == qb);
#pragma unroll
        for (int i = 0; i < 4; i++) {
            float mx = -1e30f;
#pragma unroll
            for (int jj = 0; jj < 4; jj++) {
                float v = s[i][jj] * 0.125f;
                if (diag && (c0 + jj) > (r0 + i)) v = -1e30f;
                s[i][jj] = v;
                mx = fmaxf(mx, v);
            }
#pragma unroll
            for (int off = 8; off; off >>= 1)
                mx = fmaxf(mx, __shfl_xor_sync(0xffffffffu, mx, off));
            float mnew  = fmaxf(m[i], mx);
            float alpha = __expf(m[i] - mnew);
            m[i] = mnew;
            float rs = 0.f;
#pragma unroll
            for (int jj = 0; jj < 4; jj++) {
                float p = __expf(s[i][jj] - mnew);
                Ps[(r0 + i) * PAD + c0 + jj] = p;
                rs += p;
            }
#pragma unroll
            for (int off = 8; off; off >>= 1)
                rs += __shfl_xor_sync(0xffffffffu, rs, off);
            l[i] = l[i] * alpha + rs;
#pragma unroll
            for (int jj = 0; jj < 4; jj++) o[i][jj] *= alpha;
        }
        __syncthreads();

#pragma unroll 8
        for (int k = 0; k < 64; k++) {
            float pr[4], vc[4];
#pragma unroll
            for (int i = 0; i < 4; i++) pr[i] = Ps[(r0 + i) * PAD + k];
#pragma unroll
            for (int jj = 0; jj < 4; jj++) vc[jj] = Vs[k * PAD + c0 + jj];
#pragma unroll
            for (int i = 0; i < 4; i++)
#pragma unroll
                for (int jj = 0; jj < 4; jj++)
                    o[i][jj] = fmaf(pr[i], vc[jj], o[i][jj]);
        }
    }

#pragma unroll
    for (int i = 0; i < 4; i++) {
        float inv = 1.0f / l[i];
        float4 v;
        v.x = o[i][0] * inv; v.y = o[i][1] * inv;
        v.z = o[i][2] * inv; v.w = o[i][3] * inv;
        *(float4*)&g_z[((size_t)(b * SEQ + qb * 64 + r0 + i)) * DMODEL + h * DHEAD + c0] = v;
    }
}

// ---------------- launch -----------------------------------------------------
extern "C" void kernel_launch(void* const* d_in, const int* in_sizes, int n_in,
                              void* d_out, int out_size) {
    const float* x  = (const float*)d_in[0];
    const float* WQ = (const float*)d_in[1];
    const float* WK = (const float*)d_in[2];
    const float* WV = (const float*)d_in[3];
    const float* bQ = (const float*)d_in[4];
    const float* bK = (const float*)d_in[5];
    const float* bV = (const float*)d_in[6];
    const float* WO = (const float*)d_in[7];
    const float* bO = (const float*)d_in[8];
    float* out = (float*)d_out;

    __nv_bfloat16 *pxhi, *pxlo, *pWthi, *pWtlo, *pWohi, *pWolo, *pzhi, *pzlo;
    float *pbqkv, *pqkv, *pz;
    cudaGetSymbolAddress((void**)&pxhi,  g_xhi);
    cudaGetSymbolAddress((void**)&pxlo,  g_xlo);
    cudaGetSymbolAddress((void**)&pWthi, g_Wthi);
    cudaGetSymbolAddress((void**)&pWtlo, g_Wtlo);
    cudaGetSymbolAddress((void**)&pWohi, g_Wohi);
    cudaGetSymbolAddress((void**)&pWolo, g_Wolo);
    cudaGetSymbolAddress((void**)&pzhi,  g_zhi);
    cudaGetSymbolAddress((void**)&pzlo,  g_zlo);
    cudaGetSymbolAddress((void**)&pbqkv, g_bqkv);
    cudaGetSymbolAddress((void**)&pqkv,  g_qkv);
    cudaGetSymbolAddress((void**)&pz,    g_z);

    cudaFuncSetAttribute(gemm_hmma, cudaFuncAttributeMaxDynamicSharedMemorySize, GSMEM);
    cudaFuncSetAttribute(attn_kernel, cudaFuncAttributeMaxDynamicSharedMemorySize, SMEM_ATTN);

    // 1) weight repack + bf16 split; x split
    prep_weights<<<(DMODEL * DMODEL + 255) / 256, 256>>>(WQ, WK, WV, bQ, bK, bV, WO);
    convert_split<<<(MTOK * KDIM + 255) / 256, 256>>>(x, pxhi, pxlo, MTOK * KDIM);

    // 2) QKV projection (HMMA): [4096,768] @ [768,2304] + bias
    gemm_hmma<<<dim3(NQKV / 128, MTOK / 128), 256, GSMEM>>>(
        pxhi, pxlo, pWthi, pWtlo, pbqkv, pqkv, NQKV);

    // 3) causal flash attention (fp32 SIMT)
    attn_kernel<<<dim3(SEQ / 64, HEADS, BATCH), 256, SMEM_ATTN>>>();

    // 4) z split + output projection (HMMA): [4096,768] @ [768,768] + b_O
    convert_split<<<(MTOK * KDIM + 255) / 256, 256>>>(pz, pzhi, pzlo, MTOK * KDIM);
    gemm_hmma<<<dim3(DMODEL / 128, MTOK / 128), 256, GSMEM>>>(
        pzhi, pzlo, pWohi, pWolo, bO, out, DMODEL);
}

// round 6
// speedup vs baseline: 2.2662x; 1.7300x over previous
#include <cuda_runtime.h>
#include <cuda_bf16.h>

#define BATCH  2
#define SEQ    2048
#define HEADS  12
#define DHEAD  64
#define DMODEL 768
#define NQKV   2304
#define MTOK   4096
#define KDIM   768

// ---------------- device scratch -------------------------------------------
__device__ __align__(16) __nv_bfloat16 g_xhi[(size_t)MTOK * KDIM];
__device__ __align__(16) __nv_bfloat16 g_xlo[(size_t)MTOK * KDIM];
__device__ __align__(16) __nv_bfloat16 g_Wthi[(size_t)NQKV * KDIM];  // [n][k]
__device__ __align__(16) __nv_bfloat16 g_Wtlo[(size_t)NQKV * KDIM];
__device__ __align__(16) __nv_bfloat16 g_Wohi[(size_t)DMODEL * KDIM];
__device__ __align__(16) __nv_bfloat16 g_Wolo[(size_t)DMODEL * KDIM];
__device__ __align__(16) __nv_bfloat16 g_qkvhi[(size_t)MTOK * NQKV]; // q|k|v bf16 hi
__device__ __align__(16) __nv_bfloat16 g_qkvlo[(size_t)MTOK * NQKV];
__device__ __align__(16) __nv_bfloat16 g_zhi[(size_t)MTOK * KDIM];
__device__ __align__(16) __nv_bfloat16 g_zlo[(size_t)MTOK * KDIM];
__device__ float g_bqkv[NQKV];

__device__ __forceinline__ void split2(float v, __nv_bfloat16& h, __nv_bfloat16& l) {
    h = __float2bfloat16(v);
    l = __float2bfloat16(v - __bfloat162float(h));
}
__device__ __forceinline__ unsigned smem_u32(const void* p) {
    unsigned a;
    asm("{ .reg .u64 t; cvta.to.shared.u64 t, %1; cvt.u32.u64 %0, t; }" : "=r"(a) : "l"(p));
    return a;
}
__device__ __forceinline__ unsigned pack_bf2(__nv_bfloat16 lo, __nv_bfloat16 hi) {
    unsigned short a = *(unsigned short*)&lo, b = *(unsigned short*)&hi;
    return (unsigned)a | ((unsigned)b << 16);
}
// FFMA-only exp (avoids MUFU bottleneck): exp(x) = 2^(x*log2e), deg-5 poly.
__device__ __forceinline__ float fast_exp(float x) {
    x = fmaxf(x, -87.0f);
    float y = x * 1.4426950408889634f;
    int   n = __float2int_rn(y);
    float f = y - (float)n;
    float p = 0.00133335581f;
    p = fmaf(p, f, 0.00961812911f);
    p = fmaf(p, f, 0.0555041087f);
    p = fmaf(p, f, 0.240226507f);
    p = fmaf(p, f, 0.69314718056f);
    p = fmaf(p, f, 1.0f);
    return p * __int_as_float((n + 127) << 23);
}

// ---------------- HMMA primitives (validated in round 5) --------------------
__device__ __forceinline__ void cp16(unsigned saddr, const void* gaddr) {
    asm volatile("cp.async.cg.shared.global [%0], [%1], 16;" :: "r"(saddr), "l"(gaddr));
}
__device__ __forceinline__ void cp_commit() { asm volatile("cp.async.commit_group;"); }
template <int N>
__device__ __forceinline__ void cp_wait() { asm volatile("cp.async.wait_group %0;" :: "n"(N)); }

__device__ __forceinline__ void ldsm_x4(unsigned addr, unsigned& r0, unsigned& r1,
                                        unsigned& r2, unsigned& r3) {
    asm volatile("ldmatrix.sync.aligned.m8n8.x4.shared.b16 {%0,%1,%2,%3}, [%4];"
                 : "=r"(r0), "=r"(r1), "=r"(r2), "=r"(r3) : "r"(addr));
}
__device__ __forceinline__ void ldsm_x2(unsigned addr, unsigned& r0, unsigned& r1) {
    asm volatile("ldmatrix.sync.aligned.m8n8.x2.shared.b16 {%0,%1}, [%2];"
                 : "=r"(r0), "=r"(r1) : "r"(addr));
}
__device__ __forceinline__ void ldsm_x2t(unsigned addr, unsigned& r0, unsigned& r1) {
    asm volatile("ldmatrix.sync.aligned.m8n8.x2.trans.shared.b16 {%0,%1}, [%2];"
                 : "=r"(r0), "=r"(r1) : "r"(addr));
}
__device__ __forceinline__ void mma_bf16(float* d, const unsigned* a, const unsigned* b) {
    asm volatile("mma.sync.aligned.m16n8k16.row.col.f32.bf16.bf16.f32 "
                 "{%0,%1,%2,%3}, {%4,%5,%6,%7}, {%8,%9}, {%0,%1,%2,%3};"
                 : "+f"(d[0]), "+f"(d[1]), "+f"(d[2]), "+f"(d[3])
                 : "r"(a[0]), "r"(a[1]), "r"(a[2]), "r"(a[3]), "r"(b[0]), "r"(b[1]));
}

// ---------------- weight repack + bf16 split --------------------------------
__global__ void prep_weights(const float* __restrict__ WQ, const float* __restrict__ WK,
                             const float* __restrict__ WV, const float* __restrict__ bQ,
                             const float* __restrict__ bK, const float* __restrict__ bV,
                             const float* __restrict__ WO) {
    int idx = blockIdx.x * blockDim.x + threadIdx.x;
    if (idx >= DMODEL * DMODEL) return;
    int h = idx / (DMODEL * DHEAD);
    int r = idx % (DMODEL * DHEAD);
    int dm = r / DHEAD, dk = r % DHEAD;
    int n = h * DHEAD + dk;
    __nv_bfloat16 hi, lo;
    split2(WQ[idx], hi, lo);
    g_Wthi[(size_t)n * KDIM + dm] = hi;                 g_Wtlo[(size_t)n * KDIM + dm] = lo;
    split2(WK[idx], hi, lo);
    g_Wthi[(size_t)(n + DMODEL) * KDIM + dm] = hi;      g_Wtlo[(size_t)(n + DMODEL) * KDIM + dm] = lo;
    split2(WV[idx], hi, lo);
    g_Wthi[(size_t)(n + 2 * DMODEL) * KDIM + dm] = hi;  g_Wtlo[(size_t)(n + 2 * DMODEL) * KDIM + dm] = lo;
    int kk = idx / DMODEL, nn = idx % DMODEL;
    split2(WO[idx], hi, lo);
    g_Wohi[(size_t)nn * KDIM + kk] = hi;
    g_Wolo[(size_t)nn * KDIM + kk] = lo;
    if (idx < DMODEL) {
        g_bqkv[idx] = bQ[idx];
        g_bqkv[idx + DMODEL] = bK[idx];
        g_bqkv[idx + 2 * DMODEL] = bV[idx];
    }
}

__global__ void convert_split(const float* __restrict__ src, __nv_bfloat16* __restrict__ hi,
                              __nv_bfloat16* __restrict__ lo, int n) {
    int i = blockIdx.x * blockDim.x + threadIdx.x;
    if (i < n) split2(src[i], hi[i], lo[i]);
}

// ---------------- HMMA GEMM (3-pass hi/lo split) -----------------------------
#define BK      64
#define LDS_PAD 8
#define LDS_STR (BK + LDS_PAD)
#define STAGE_B (2 * 128 * LDS_STR * 2)
#define GSMEM   (2 * STAGE_B)

__device__ __forceinline__ void load_stage(unsigned sA, unsigned sB,
                                           const __nv_bfloat16* __restrict__ A,
                                           const __nv_bfloat16* __restrict__ B,
                                           int arow0, int brow0, int k0, int tid) {
#pragma unroll
    for (int t = 0; t < 4; t++) {
        int i = tid + t * 256;
        int row = i >> 3, seg = i & 7;
        cp16(sA + row * (LDS_STR * 2) + seg * 16,
             A + (size_t)(arow0 + row) * KDIM + k0 + seg * 8);
        cp16(sB + row * (LDS_STR * 2) + seg * 16,
             B + (size_t)(brow0 + row) * KDIM + k0 + seg * 8);
    }
    cp_commit();
}

template <bool SPLIT>
__global__ __launch_bounds__(256, 2)
void gemm_hmma(const __nv_bfloat16* __restrict__ Ahi, const __nv_bfloat16* __restrict__ Alo,
               const __nv_bfloat16* __restrict__ Bhi, const __nv_bfloat16* __restrict__ Blo,
               const float* __restrict__ bias, float* __restrict__ C,
               __nv_bfloat16* __restrict__ Chi, __nv_bfloat16* __restrict__ Clo, int Nglob) {
    extern __shared__ char smem[];
    const unsigned sb = smem_u32(smem);
    const int tid = threadIdx.x, wid = tid >> 5, lane = tid & 31;
    const int brow = blockIdx.y * 128, bcol = blockIdx.x * 128;
    const int wm = (wid & 1) * 64, wn = (wid >> 1) * 32;

    const __nv_bfloat16* Aps[3] = {Ahi, Ahi, Alo};
    const __nv_bfloat16* Bps[3] = {Bhi, Blo, Bhi};

    const int NSTAGE = 3 * (KDIM / BK);
    float acc[4][4][4] = {};
    const int a_r = lane & 15, a_h = lane >> 4;
    const int b_r = lane & 7,  b_h = (lane >> 3) & 1;

    load_stage(sb, sb + 128 * LDS_STR * 2, Aps[0], Bps[0], brow, bcol, 0, tid);

    for (int s = 0; s < NSTAGE; s++) {
        const int buf = s & 1;
        if (s + 1 < NSTAGE) {
            const int p = (s + 1) / (KDIM / BK), k0 = ((s + 1) % (KDIM / BK)) * BK;
            const unsigned off = (1 - buf) * STAGE_B;
            load_stage(sb + off, sb + off + 128 * LDS_STR * 2, Aps[p], Bps[p],
                       brow, bcol, k0, tid);
            cp_wait<1>();
        } else {
            cp_wait<0>();
        }
        __syncthreads();

        const unsigned sA = sb + buf * STAGE_B;
        const unsigned sB = sA + 128 * LDS_STR * 2;
#pragma unroll
        for (int kk = 0; kk < BK; kk += 16) {
            unsigned a[4][4], b[4][2];
#pragma unroll
            for (int mf = 0; mf < 4; mf++)
                ldsm_x4(sA + (wm + mf * 16 + a_r) * (LDS_STR * 2) + (kk + a_h * 8) * 2,
                        a[mf][0], a[mf][1], a[mf][2], a[mf][3]);
#pragma unroll
            for (int nf = 0; nf < 4; nf++)
                ldsm_x2(sB + (wn + nf * 8 + b_r) * (LDS_STR * 2) + (kk + b_h * 8) * 2,
                        b[nf][0], b[nf][1]);
#pragma unroll
            for (int mf = 0; mf < 4; mf++)
#pragma unroll
                for (int nf = 0; nf < 4; nf++)
                    mma_bf16(acc[mf][nf], a[mf], b[nf]);
        }
        __syncthreads();
    }

    const int grp = lane >> 2, tig = lane & 3;
#pragma unroll
    for (int mf = 0; mf < 4; mf++) {
#pragma unroll
        for (int nf = 0; nf < 4; nf++) {
            const int r1 = brow + wm + mf * 16 + grp;
            const int cc = bcol + wn + nf * 8 + tig * 2;
            float v0 = acc[mf][nf][0] + bias[cc];
            float v1 = acc[mf][nf][1] + bias[cc + 1];
            float v2 = acc[mf][nf][2] + bias[cc];
            float v3 = acc[mf][nf][3] + bias[cc + 1];
            if (SPLIT) {
                __nv_bfloat16 h0, l0_, h1, l1_;
                __nv_bfloat162 ph, pl;
                split2(v0, h0, l0_); split2(v1, h1, l1_);
                ph.x = h0; ph.y = h1; pl.x = l0_; pl.y = l1_;
                *(__nv_bfloat162*)&Chi[(size_t)r1 * Nglob + cc] = ph;
                *(__nv_bfloat162*)&Clo[(size_t)r1 * Nglob + cc] = pl;
                split2(v2, h0, l0_); split2(v3, h1, l1_);
                ph.x = h0; ph.y = h1; pl.x = l0_; pl.y = l1_;
                *(__nv_bfloat162*)&Chi[(size_t)(r1 + 8) * Nglob + cc] = ph;
                *(__nv_bfloat162*)&Clo[(size_t)(r1 + 8) * Nglob + cc] = pl;
            } else {
                float2 w0, w1;
                w0.x = v0; w0.y = v1; w1.x = v2; w1.y = v3;
                *(float2*)&C[(size_t)r1 * Nglob + cc] = w0;
                *(float2*)&C[(size_t)(r1 + 8) * Nglob + cc] = w1;
            }
        }
    }
}

// ---------------- tensor-core flash attention --------------------------------
// 128-row Q block, 64-key tiles, 8 warps x 16 rows, bf16 3-pass both matmuls.
#define A_STRB   144                        // 72 bf16 row stride (pad 8)
#define A_QBYTES (128 * A_STRB)             // 18432 per Q plane
#define A_KVARR  (64 * A_STRB)              // 9216 per KV plane
#define A_KVBUF  (4 * A_KVARR)              // Khi,Klo,Vhi,Vlo
#define A_SMEM   (2 * A_QBYTES + 2 * A_KVBUF)  // 110592

__device__ __forceinline__ void attn_load_kv(unsigned dst,
                                             const __nv_bfloat16* __restrict__ qh,
                                             const __nv_bfloat16* __restrict__ ql,
                                             size_t tokk, int hq, int tid) {
#pragma unroll
    for (int t = 0; t < 8; t++) {
        int i = tid + t * 256;              // 0..2047
        int arr = i >> 9;                   // 0:Khi 1:Klo 2:Vhi 3:Vlo
        int r = (i >> 3) & 63, seg = i & 7;
        const __nv_bfloat16* s = (arr & 1) ? ql : qh;
        int col = ((arr < 2) ? DMODEL : 2 * DMODEL) + hq + seg * 8;
        cp16(dst + arr * A_KVARR + r * A_STRB + seg * 16,
             s + (tokk + r) * NQKV + col);
    }
}

__global__ __launch_bounds__(256)
void attn_hmma(const __nv_bfloat16* __restrict__ qh,
               const __nv_bfloat16* __restrict__ ql) {
    extern __shared__ char smc[];
    const unsigned sb = smem_u32(smc);
    const unsigned sQh = sb, sQl = sb + A_QBYTES;
    const unsigned sKV = sb + 2 * A_QBYTES;
    const int tid = threadIdx.x, wid = tid >> 5, lane = tid & 31;
    const int qb = blockIdx.x, h = blockIdx.y, bb = blockIdx.z;
    const int hq = h * 64;
    const size_t tok0 = (size_t)bb * SEQ + (size_t)qb * 128;

    // Q hi/lo into smem
#pragma unroll
    for (int t = 0; t < 8; t++) {
        int i = tid + t * 256;
        int arr = i >> 10, r = (i >> 3) & 127, seg = i & 7;
        const __nv_bfloat16* s = arr ? ql : qh;
        cp16(sQh + arr * A_QBYTES + r * A_STRB + seg * 16,
             s + (tok0 + r) * NQKV + hq + seg * 8);
    }
    attn_load_kv(sKV, qh, ql, (size_t)bb * SEQ, hq, tid);
    cp_commit();

    const int a_r = lane & 15, a_h = lane >> 4;
    const int b_r = lane & 7, b_h = (lane >> 3) & 1;
    const int grp = lane >> 2;
    const int tig = lane & 3;
    const int myrow = qb * 128 + wid * 16 + grp;

    float m0 = -1e30f, m1 = -1e30f, l0 = 0.f, l1 = 0.f;
    float z[8][4] = {};

    const int ntiles = 2 * qb + 2;
    for (int j = 0; j < ntiles; j++) {
        if (j + 1 < ntiles) {
            attn_load_kv(sKV + ((j + 1) & 1) * A_KVBUF, qh, ql,
                         (size_t)bb * SEQ + (size_t)(j + 1) * 64, hq, tid);
            cp_commit();
            cp_wait<1>();
        } else {
            cp_wait<0>();
        }
        __syncthreads();

        const unsigned bkv = sKV + (j & 1) * A_KVBUF;
        const unsigned sKh = bkv, sKl = bkv + A_KVARR;
        const unsigned sVh = bkv + 2 * A_KVARR, sVl = bkv + 3 * A_KVARR;

        // S = Q K^T (3 passes)
        float sc[8][4] = {};
#pragma unroll
        for (int kk = 0; kk < 64; kk += 16) {
            unsigned aH[4], aL[4];
            ldsm_x4(sQh + (wid * 16 + a_r) * A_STRB + (kk + a_h * 8) * 2,
                    aH[0], aH[1], aH[2], aH[3]);
            ldsm_x4(sQl + (wid * 16 + a_r) * A_STRB + (kk + a_h * 8) * 2,
                    aL[0], aL[1], aL[2], aL[3]);
#pragma unroll
            for (int nf = 0; nf < 8; nf++) {
                unsigned bH[2], bL[2];
                ldsm_x2(sKh + (nf * 8 + b_r) * A_STRB + (kk + b_h * 8) * 2, bH[0], bH[1]);
                ldsm_x2(sKl + (nf * 8 + b_r) * A_STRB + (kk + b_h * 8) * 2, bL[0], bL[1]);
                mma_bf16(sc[nf], aH, bH);
                mma_bf16(sc[nf], aH, bL);
                mma_bf16(sc[nf], aL, bH);
            }
        }

        // scale + causal mask
        const int key0 = j * 64;
        const bool maskt = (j >= 2 * qb);
#pragma unroll
        for (int nf = 0; nf < 8; nf++) {
#pragma unroll
            for (int e = 0; e < 4; e++) {
                float v = sc[nf][e] * 0.125f;
                if (maskt) {
                    int col = key0 + nf * 8 + tig * 2 + (e & 1);
                    int rr = myrow + (e >> 1) * 8;
                    if (col > rr) v = -1e9f;
                }
                sc[nf][e] = v;
            }
        }
        // online softmax (rows grp, grp+8; quad = 4 threads per row)
        float mx0 = -1e30f, mx1 = -1e30f;
#pragma unroll
        for (int nf = 0; nf < 8; nf++) {
            mx0 = fmaxf(mx0, fmaxf(sc[nf][0], sc[nf][1]));
            mx1 = fmaxf(mx1, fmaxf(sc[nf][2], sc[nf][3]));
        }
        mx0 = fmaxf(mx0, __shfl_xor_sync(0xffffffffu, mx0, 1));
        mx0 = fmaxf(mx0, __shfl_xor_sync(0xffffffffu, mx0, 2));
        mx1 = fmaxf(mx1, __shfl_xor_sync(0xffffffffu, mx1, 1));
        mx1 = fmaxf(mx1, __shfl_xor_sync(0xffffffffu, mx1, 2));
        float nm0 = fmaxf(m0, mx0), nm1 = fmaxf(m1, mx1);
        float al0 = fast_exp(m0 - nm0), al1 = fast_exp(m1 - nm1);
        m0 = nm0; m1 = nm1;

        float rs0 = 0.f, rs1 = 0.f;
        unsigned pH0[8], pH1[8], pL0[8], pL1[8];
#pragma unroll
        for (int nf = 0; nf < 8; nf++) {
            float p00 = fast_exp(sc[nf][0] - nm0);
            float p01 = fast_exp(sc[nf][1] - nm0);
            float p10 = fast_exp(sc[nf][2] - nm1);
            float p11 = fast_exp(sc[nf][3] - nm1);
            rs0 += p00 + p01; rs1 += p10 + p11;
            __nv_bfloat16 h00 = __float2bfloat16(p00), h01 = __float2bfloat16(p01);
            __nv_bfloat16 h10 = __float2bfloat16(p10), h11 = __float2bfloat16(p11);
            pH0[nf] = pack_bf2(h00, h01);
            pH1[nf] = pack_bf2(h10, h11);
            pL0[nf] = pack_bf2(__float2bfloat16(p00 - __bfloat162float(h00)),
                               __float2bfloat16(p01 - __bfloat162float(h01)));
            pL1[nf] = pack_bf2(__float2bfloat16(p10 - __bfloat162float(h10)),
                               __float2bfloat16(p11 - __bfloat162float(h11)));
        }
        rs0 += __shfl_xor_sync(0xffffffffu, rs0, 1);
        rs0 += __shfl_xor_sync(0xffffffffu, rs0, 2);
        rs1 += __shfl_xor_sync(0xffffffffu, rs1, 1);
        rs1 += __shfl_xor_sync(0xffffffffu, rs1, 2);
        l0 = l0 * al0 + rs0; l1 = l1 * al1 + rs1;
#pragma unroll
        for (int nf = 0; nf < 8; nf++) {
            z[nf][0] *= al0; z[nf][1] *= al0; z[nf][2] *= al1; z[nf][3] *= al1;
        }

        // z += P V (3 passes; V via ldmatrix.trans)
#pragma unroll
        for (int c = 0; c < 4; c++) {
            unsigned aH[4] = {pH0[2 * c], pH1[2 * c], pH0[2 * c + 1], pH1[2 * c + 1]};
            unsigned aL[4] = {pL0[2 * c], pL1[2 * c], pL0[2 * c + 1], pL1[2 * c + 1]};
#pragma unroll
            for (int nf = 0; nf < 8; nf++) {
                unsigned bh[2], bl[2];
                ldsm_x2t(sVh + (c * 16 + a_r) * A_STRB + nf * 16, bh[0], bh[1]);
                ldsm_x2t(sVl + (c * 16 + a_r) * A_STRB + nf * 16, bl[0], bl[1]);
                mma_bf16(z[nf], aH, bh);
                mma_bf16(z[nf], aH, bl);
                mma_bf16(z[nf], aL, bh);
            }
        }
        __syncthreads();
    }

    // epilogue: normalize, split to bf16 hi/lo z
    float i0 = 1.f / l0, i1 = 1.f / l1;
    size_t t0 = tok0 + wid * 16 + grp;
#pragma unroll
    for (int nf = 0; nf < 8; nf++) {
        int d = hq + nf * 8 + tig * 2;
        __nv_bfloat16 hA, lA, hB, lB;
        __nv_bfloat162 ph, pl;
        split2(z[nf][0] * i0, hA, lA); split2(z[nf][1] * i0, hB, lB);
        ph.x = hA; ph.y = hB; pl.x = lA; pl.y = lB;
        *(__nv_bfloat162*)&g_zhi[t0 * KDIM + d] = ph;
        *(__nv_bfloat162*)&g_zlo[t0 * KDIM + d] = pl;
        split2(z[nf][2] * i1, hA, lA); split2(z[nf][3] * i1, hB, lB);
        ph.x = hA; ph.y = hB; pl.x = lA; pl.y = lB;
        *(__nv_bfloat162*)&g_zhi[(t0 + 8) * KDIM + d] = ph;
        *(__nv_bfloat162*)&g_zlo[(t0 + 8) * KDIM + d] = pl;
    }
}

// ---------------- launch -----------------------------------------------------
extern "C" void kernel_launch(void* const* d_in, const int* in_sizes, int n_in,
                              void* d_out, int out_size) {
    const float* x  = (const float*)d_in[0];
    const float* WQ = (const float*)d_in[1];
    const float* WK = (const float*)d_in[2];
    const float* WV = (const float*)d_in[3];
    const float* bQ = (const float*)d_in[4];
    const float* bK = (const float*)d_in[5];
    const float* bV = (const float*)d_in[6];
    const float* WO = (const float*)d_in[7];
    const float* bO = (const float*)d_in[8];
    float* out = (float*)d_out;

    __nv_bfloat16 *pxhi, *pxlo, *pWthi, *pWtlo, *pWohi, *pWolo, *pqh, *pql, *pzhi, *pzlo;
    float* pbqkv;
    cudaGetSymbolAddress((void**)&pxhi,  g_xhi);
    cudaGetSymbolAddress((void**)&pxlo,  g_xlo);
    cudaGetSymbolAddress((void**)&pWthi, g_Wthi);
    cudaGetSymbolAddress((void**)&pWtlo, g_Wtlo);
    cudaGetSymbolAddress((void**)&pWohi, g_Wohi);
    cudaGetSymbolAddress((void**)&pWolo, g_Wolo);
    cudaGetSymbolAddress((void**)&pqh,   g_qkvhi);
    cudaGetSymbolAddress((void**)&pql,   g_qkvlo);
    cudaGetSymbolAddress((void**)&pzhi,  g_zhi);
    cudaGetSymbolAddress((void**)&pzlo,  g_zlo);
    cudaGetSymbolAddress((void**)&pbqkv, g_bqkv);

    cudaFuncSetAttribute(gemm_hmma<true>,  cudaFuncAttributeMaxDynamicSharedMemorySize, GSMEM);
    cudaFuncSetAttribute(gemm_hmma<false>, cudaFuncAttributeMaxDynamicSharedMemorySize, GSMEM);
    cudaFuncSetAttribute(attn_hmma, cudaFuncAttributeMaxDynamicSharedMemorySize, A_SMEM);

    // 1) weight repack + x split
    prep_weights<<<(DMODEL * DMODEL + 255) / 256, 256>>>(WQ, WK, WV, bQ, bK, bV, WO);
    convert_split<<<(MTOK * KDIM + 255) / 256, 256>>>(x, pxhi, pxlo, MTOK * KDIM);

    // 2) QKV projection -> bf16 hi/lo qkv
    gemm_hmma<true><<<dim3(NQKV / 128, MTOK / 128), 256, GSMEM>>>(
        pxhi, pxlo, pWthi, pWtlo, pbqkv, nullptr, pqh, pql, NQKV);

    // 3) tensor-core causal flash attention -> bf16 hi/lo z
    attn_hmma<<<dim3(SEQ / 128, HEADS, BATCH), 256, A_SMEM>>>(pqh, pql);

    // 4) output projection (fp32 out)
    gemm_hmma<false><<<dim3(DMODEL / 128, MTOK / 128), 256, GSMEM>>>(
        pzhi, pzlo, pWohi, pWolo, bO, out, nullptr, nullptr, DMODEL);
}

// round 10
// speedup vs baseline: 2.3986x; 1.0584x over previous
#include <cuda_runtime.h>
#include <cuda_bf16.h>

#define BATCH  2
#define SEQ    2048
#define HEADS  12
#define DHEAD  64
#define DMODEL 768
#define NQKV   2304
#define MTOK   4096
#define KDIM   768

// ---------------- device scratch -------------------------------------------
__device__ __align__(16) __nv_bfloat16 g_xhi[(size_t)MTOK * KDIM];
__device__ __align__(16) __nv_bfloat16 g_xlo[(size_t)MTOK * KDIM];
__device__ __align__(16) __nv_bfloat16 g_Wthi[(size_t)NQKV * KDIM];  // [n][k]
__device__ __align__(16) __nv_bfloat16 g_Wtlo[(size_t)NQKV * KDIM];
__device__ __align__(16) __nv_bfloat16 g_Wohi[(size_t)DMODEL * KDIM];
__device__ __align__(16) __nv_bfloat16 g_Wolo[(size_t)DMODEL * KDIM];
__device__ __align__(16) __nv_bfloat16 g_qkvhi[(size_t)MTOK * NQKV]; // q|k|v bf16 hi
__device__ __align__(16) __nv_bfloat16 g_qkvlo[(size_t)MTOK * NQKV];
__device__ __align__(16) __nv_bfloat16 g_zhi[(size_t)MTOK * KDIM];
__device__ __align__(16) __nv_bfloat16 g_zlo[(size_t)MTOK * KDIM];
__device__ float g_bqkv[NQKV];

__device__ __forceinline__ void split2(float v, __nv_bfloat16& h, __nv_bfloat16& l) {
    h = __float2bfloat16(v);
    l = __float2bfloat16(v - __bfloat162float(h));
}
__device__ __forceinline__ unsigned smem_u32(const void* p) {
    unsigned a;
    asm("{ .reg .u64 t; cvta.to.shared.u64 t, %1; cvt.u32.u64 %0, t; }" : "=r"(a) : "l"(p));
    return a;
}
__device__ __forceinline__ unsigned pack_bf2(__nv_bfloat16 lo, __nv_bfloat16 hi) {
    unsigned short a = *(unsigned short*)&lo, b = *(unsigned short*)&hi;
    return (unsigned)a | ((unsigned)b << 16);
}
// FFMA-only exp (avoids MUFU bottleneck): exp(x) = 2^(x*log2e), deg-5 poly.
__device__ __forceinline__ float fast_exp(float x) {
    x = fmaxf(x, -87.0f);
    float y = x * 1.4426950408889634f;
    int   n = __float2int_rn(y);
    float f = y - (float)n;
    float p = 0.00133335581f;
    p = fmaf(p, f, 0.00961812911f);
    p = fmaf(p, f, 0.0555041087f);
    p = fmaf(p, f, 0.240226507f);
    p = fmaf(p, f, 0.69314718056f);
    p = fmaf(p, f, 1.0f);
    return p * __int_as_float((n + 127) << 23);
}

// ---------------- HMMA primitives ------------------------------------------
__device__ __forceinline__ void cp16(unsigned saddr, const void* gaddr) {
    asm volatile("cp.async.cg.shared.global [%0], [%1], 16;" :: "r"(saddr), "l"(gaddr));
}
__device__ __forceinline__ void cp_commit() { asm volatile("cp.async.commit_group;"); }
template <int N>
__device__ __forceinline__ void cp_wait() { asm volatile("cp.async.wait_group %0;" :: "n"(N)); }

__device__ __forceinline__ void ldsm_x4(unsigned addr, unsigned& r0, unsigned& r1,
                                        unsigned& r2, unsigned& r3) {
    asm volatile("ldmatrix.sync.aligned.m8n8.x4.shared.b16 {%0,%1,%2,%3}, [%4];"
                 : "=r"(r0), "=r"(r1), "=r"(r2), "=r"(r3) : "r"(addr));
}
__device__ __forceinline__ void ldsm_x2(unsigned addr, unsigned& r0, unsigned& r1) {
    asm volatile("ldmatrix.sync.aligned.m8n8.x2.shared.b16 {%0,%1}, [%2];"
                 : "=r"(r0), "=r"(r1) : "r"(addr));
}
__device__ __forceinline__ void ldsm_x2t(unsigned addr, unsigned& r0, unsigned& r1) {
    asm volatile("ldmatrix.sync.aligned.m8n8.x2.trans.shared.b16 {%0,%1}, [%2];"
                 : "=r"(r0), "=r"(r1) : "r"(addr));
}
__device__ __forceinline__ void mma_bf16(float* d, const unsigned* a, const unsigned* b) {
    asm volatile("mma.sync.aligned.m16n8k16.row.col.f32.bf16.bf16.f32 "
                 "{%0,%1,%2,%3}, {%4,%5,%6,%7}, {%8,%9}, {%0,%1,%2,%3};"
                 : "+f"(d[0]), "+f"(d[1]), "+f"(d[2]), "+f"(d[3])
                 : "r"(a[0]), "r"(a[1]), "r"(a[2]), "r"(a[3]), "r"(b[0]), "r"(b[1]));
}

// ---------------- weight repack + bf16 split --------------------------------
// W_Q and b_Q are pre-scaled by 1/sqrt(d_head)=0.125 so attention skips scaling.
__global__ void prep_weights(const float* __restrict__ WQ, const float* __restrict__ WK,
                             const float* __restrict__ WV, const float* __restrict__ bQ,
                             const float* __restrict__ bK, const float* __restrict__ bV,
                             const float* __restrict__ WO) {
    int idx = blockIdx.x * blockDim.x + threadIdx.x;
    if (idx >= DMODEL * DMODEL) return;
    int h = idx / (DMODEL * DHEAD);
    int r = idx % (DMODEL * DHEAD);
    int dm = r / DHEAD, dk = r % DHEAD;
    int n = h * DHEAD + dk;
    __nv_bfloat16 hi, lo;
    split2(WQ[idx] * 0.125f, hi, lo);
    g_Wthi[(size_t)n * KDIM + dm] = hi;                 g_Wtlo[(size_t)n * KDIM + dm] = lo;
    split2(WK[idx], hi, lo);
    g_Wthi[(size_t)(n + DMODEL) * KDIM + dm] = hi;      g_Wtlo[(size_t)(n + DMODEL) * KDIM + dm] = lo;
    split2(WV[idx], hi, lo);
    g_Wthi[(size_t)(n + 2 * DMODEL) * KDIM + dm] = hi;  g_Wtlo[(size_t)(n + 2 * DMODEL) * KDIM + dm] = lo;
    int kk = idx / DMODEL, nn = idx % DMODEL;
    split2(WO[idx], hi, lo);
    g_Wohi[(size_t)nn * KDIM + kk] = hi;
    g_Wolo[(size_t)nn * KDIM + kk] = lo;
    if (idx < DMODEL) {
        g_bqkv[idx] = bQ[idx] * 0.125f;
        g_bqkv[idx + DMODEL] = bK[idx];
        g_bqkv[idx + 2 * DMODEL] = bV[idx];
    }
}

__global__ void convert_split(const float* __restrict__ src, __nv_bfloat16* __restrict__ hi,
                              __nv_bfloat16* __restrict__ lo, int n) {
    int i = blockIdx.x * blockDim.x + threadIdx.x;
    if (i < n) split2(src[i], hi[i], lo[i]);
}

// ---------------- HMMA GEMM (3-pass hi/lo split, 3-stage pipeline) -----------
#define BK      64
#define LDS_PAD 8
#define LDS_STR (BK + LDS_PAD)
#define STAGE_B (2 * 128 * LDS_STR * 2)   // 36864: A plane + B plane
#define NSTG    3
#define GSMEM   (NSTG * STAGE_B)          // 110592

__device__ __forceinline__ void load_stage(unsigned sA, unsigned sB,
                                           const __nv_bfloat16* __restrict__ A,
                                           const __nv_bfloat16* __restrict__ B,
                                           int arow0, int brow0, int k0, int tid) {
#pragma unroll
    for (int t = 0; t < 4; t++) {
        int i = tid + t * 256;
        int row = i >> 3, seg = i & 7;
        cp16(sA + row * (LDS_STR * 2) + seg * 16,
             A + (size_t)(arow0 + row) * KDIM + k0 + seg * 8);
        cp16(sB + row * (LDS_STR * 2) + seg * 16,
             B + (size_t)(brow0 + row) * KDIM + k0 + seg * 8);
    }
    cp_commit();
}

template <bool SPLIT>
__global__ __launch_bounds__(256, 2)
void gemm_hmma(const __nv_bfloat16* __restrict__ Ahi, const __nv_bfloat16* __restrict__ Alo,
               const __nv_bfloat16* __restrict__ Bhi, const __nv_bfloat16* __restrict__ Blo,
               const float* __restrict__ bias, float* __restrict__ C,
               __nv_bfloat16* __restrict__ Chi, __nv_bfloat16* __restrict__ Clo, int Nglob) {
    extern __shared__ char smem[];
    const unsigned sb = smem_u32(smem);
    const int tid = threadIdx.x, wid = tid >> 5, lane = tid & 31;
    const int brow = blockIdx.y * 128, bcol = blockIdx.x * 128;
    const int wm = (wid & 1) * 64, wn = (wid >> 1) * 32;

    const __nv_bfloat16* Aps[3] = {Ahi, Ahi, Alo};
    const __nv_bfloat16* Bps[3] = {Bhi, Blo, Bhi};

    const int NSTAGE = 3 * (KDIM / BK);   // 36
    float acc[4][4][4] = {};
    const int a_r = lane & 15, a_h = lane >> 4;
    const int b_r = lane & 7,  b_h = (lane >> 3) & 1;

    // prologue: stages 0 and 1 in flight
    load_stage(sb, sb + 128 * LDS_STR * 2, Aps[0], Bps[0], brow, bcol, 0, tid);
    load_stage(sb + STAGE_B, sb + STAGE_B + 128 * LDS_STR * 2, Aps[0], Bps[0],
               brow, bcol, BK, tid);

    for (int s = 0; s < NSTAGE; s++) {
        if (s + 1 < NSTAGE) cp_wait<1>(); else cp_wait<0>();
        __syncthreads();
        if (s + 2 < NSTAGE) {
            const int p = (s + 2) / (KDIM / BK), k0 = ((s + 2) % (KDIM / BK)) * BK;
            const unsigned off = ((s + 2) % NSTG) * STAGE_B;
            load_stage(sb + off, sb + off + 128 * LDS_STR * 2, Aps[p], Bps[p],
                       brow, bcol, k0, tid);
        }
        const unsigned sA = sb + (s % NSTG) * STAGE_B;
        const unsigned sB = sA + 128 * LDS_STR * 2;
#pragma unroll
        for (int kk = 0; kk < BK; kk += 16) {
            unsigned a[4][4], b[4][2];
#pragma unroll
            for (int mf = 0; mf < 4; mf++)
                ldsm_x4(sA + (wm + mf * 16 + a_r) * (LDS_STR * 2) + (kk + a_h * 8) * 2,
                        a[mf][0], a[mf][1], a[mf][2], a[mf][3]);
#pragma unroll
            for (int nf = 0; nf < 4; nf++)
                ldsm_x2(sB + (wn + nf * 8 + b_r) * (LDS_STR * 2) + (kk + b_h * 8) * 2,
                        b[nf][0], b[nf][1]);
#pragma unroll
            for (int mf = 0; mf < 4; mf++)
#pragma unroll
                for (int nf = 0; nf < 4; nf++)
                    mma_bf16(acc[mf][nf], a[mf], b[nf]);
        }
    }

    const int grp = lane >> 2, tig = lane & 3;
#pragma unroll
    for (int mf = 0; mf < 4; mf++) {
#pragma unroll
        for (int nf = 0; nf < 4; nf++) {
            const int r1 = brow + wm + mf * 16 + grp;
            const int cc = bcol + wn + nf * 8 + tig * 2;
            float v0 = acc[mf][nf][0] + bias[cc];
            float v1 = acc[mf][nf][1] + bias[cc + 1];
            float v2 = acc[mf][nf][2] + bias[cc];
            float v3 = acc[mf][nf][3] + bias[cc + 1];
            if (SPLIT) {
                __nv_bfloat16 h0, l0_, h1, l1_;
                __nv_bfloat162 ph, pl;
                split2(v0, h0, l0_); split2(v1, h1, l1_);
                ph.x = h0; ph.y = h1; pl.x = l0_; pl.y = l1_;
                *(__nv_bfloat162*)&Chi[(size_t)r1 * Nglob + cc] = ph;
                *(__nv_bfloat162*)&Clo[(size_t)r1 * Nglob + cc] = pl;
                split2(v2, h0, l0_); split2(v3, h1, l1_);
                ph.x = h0; ph.y = h1; pl.x = l0_; pl.y = l1_;
                *(__nv_bfloat162*)&Chi[(size_t)(r1 + 8) * Nglob + cc] = ph;
                *(__nv_bfloat162*)&Clo[(size_t)(r1 + 8) * Nglob + cc] = pl;
            } else {
                float2 w0, w1;
                w0.x = v0; w0.y = v1; w1.x = v2; w1.y = v3;
                *(float2*)&C[(size_t)r1 * Nglob + cc] = w0;
                *(float2*)&C[(size_t)(r1 + 8) * Nglob + cc] = w1;
            }
        }
    }
}

// ---------------- tensor-core flash attention --------------------------------
#define A_STRB   144
#define A_QBYTES (128 * A_STRB)
#define A_KVARR  (64 * A_STRB)
#define A_KVBUF  (4 * A_KVARR)
#define A_SMEM   (2 * A_QBYTES + 2 * A_KVBUF)

__device__ __forceinline__ void attn_load_kv(unsigned dst,
                                             const __nv_bfloat16* __restrict__ qh,
                                             const __nv_bfloat16* __restrict__ ql,
                                             size_t tokk, int hq, int tid) {
#pragma unroll
    for (int t = 0; t < 8; t++) {
        int i = tid + t * 256;
        int arr = i >> 9;
        int r = (i >> 3) & 63, seg = i & 7;
        const __nv_bfloat16* s = (arr & 1) ? ql : qh;
        int col = ((arr < 2) ? DMODEL : 2 * DMODEL) + hq + seg * 8;
        cp16(dst + arr * A_KVARR + r * A_STRB + seg * 16,
             s + (tokk + r) * NQKV + col);
    }
}

__global__ __launch_bounds__(256)
void attn_hmma(const __nv_bfloat16* __restrict__ qh,
               const __nv_bfloat16* __restrict__ ql) {
    extern __shared__ char smc[];
    const unsigned sb = smem_u32(smc);
    const unsigned sQh = sb, sQl = sb + A_QBYTES;
    const unsigned sKV = sb + 2 * A_QBYTES;
    const int tid = threadIdx.x, wid = tid >> 5, lane = tid & 31;
    // big-first scheduling: largest causal workload launches first
    const int qb = (SEQ / 128 - 1) - blockIdx.x;
    const int h = blockIdx.y, bb = blockIdx.z;
    const int hq = h * 64;
    const size_t tok0 = (size_t)bb * SEQ + (size_t)qb * 128;

#pragma unroll
    for (int t = 0; t < 8; t++) {
        int i = tid + t * 256;
        int arr = i >> 10, r = (i >> 3) & 127, seg = i & 7;
        const __nv_bfloat16* s = arr ? ql : qh;
        cp16(sQh + arr * A_QBYTES + r * A_STRB + seg * 16,
             s + (tok0 + r) * NQKV + hq + seg * 8);
    }
    attn_load_kv(sKV, qh, ql, (size_t)bb * SEQ, hq, tid);
    cp_commit();

    const int a_r = lane & 15, a_h = lane >> 4;
    const int b_r = lane & 7, b_h = (lane >> 3) & 1;
    const int grp = lane >> 2;
    const int tig = lane & 3;
    const int myrow = qb * 128 + wid * 16 + grp;

    float m0 = -1e30f, m1 = -1e30f, l0 = 0.f, l1 = 0.f;
    float z[8][4] = {};

    const int ntiles = 2 * qb + 2;
    for (int j = 0; j < ntiles; j++) {
        if (j + 1 < ntiles) {
            attn_load_kv(sKV + ((j + 1) & 1) * A_KVBUF, qh, ql,
                         (size_t)bb * SEQ + (size_t)(j + 1) * 64, hq, tid);
            cp_commit();
            cp_wait<1>();
        } else {
            cp_wait<0>();
        }
        __syncthreads();

        const unsigned bkv = sKV + (j & 1) * A_KVBUF;
        const unsigned sKh = bkv, sKl = bkv + A_KVARR;
        const unsigned sVh = bkv + 2 * A_KVARR, sVl = bkv + 3 * A_KVARR;

        // S = Q K^T (3 passes; Q pre-scaled by 0.125)
        float sc[8][4] = {};
#pragma unroll
        for (int kk = 0; kk < 64; kk += 16) {
            unsigned aH[4], aL[4];
            ldsm_x4(sQh + (wid * 16 + a_r) * A_STRB + (kk + a_h * 8) * 2,
                    aH[0], aH[1], aH[2], aH[3]);
            ldsm_x4(sQl + (wid * 16 + a_r) * A_STRB + (kk + a_h * 8) * 2,
                    aL[0], aL[1], aL[2], aL[3]);
#pragma unroll
            for (int nf = 0; nf < 8; nf++) {
                unsigned bH[2], bL[2];
                ldsm_x2(sKh + (nf * 8 + b_r) * A_STRB + (kk + b_h * 8) * 2, bH[0], bH[1]);
                ldsm_x2(sKl + (nf * 8 + b_r) * A_STRB + (kk + b_h * 8) * 2, bL[0], bL[1]);
                mma_bf16(sc[nf], aH, bH);
                mma_bf16(sc[nf], aH, bL);
                mma_bf16(sc[nf], aL, bH);
            }
        }

        // causal mask on diagonal tiles
        const int key0 = j * 64;
        if (j >= 2 * qb) {
#pragma unroll
            for (int nf = 0; nf < 8; nf++) {
#pragma unroll
                for (int e = 0; e < 4; e++) {
                    int col = key0 + nf * 8 + tig * 2 + (e & 1);
                    int rr = myrow + (e >> 1) * 8;
                    if (col > rr) sc[nf][e] = -1e9f;
                }
            }
        }
        // online softmax
        float mx0 = -1e30f, mx1 = -1e30f;
#pragma unroll
        for (int nf = 0; nf < 8; nf++) {
            mx0 = fmaxf(mx0, fmaxf(sc[nf][0], sc[nf][1]));
            mx1 = fmaxf(mx1, fmaxf(sc[nf][2], sc[nf][3]));
        }
        mx0 = fmaxf(mx0, __shfl_xor_sync(0xffffffffu, mx0, 1));
        mx0 = fmaxf(mx0, __shfl_xor_sync(0xffffffffu, mx0, 2));
        mx1 = fmaxf(mx1, __shfl_xor_sync(0xffffffffu, mx1, 1));
        mx1 = fmaxf(mx1, __shfl_xor_sync(0xffffffffu, mx1, 2));
        float nm0 = fmaxf(m0, mx0), nm1 = fmaxf(m1, mx1);
        float al0 = fast_exp(m0 - nm0), al1 = fast_exp(m1 - nm1);
        m0 = nm0; m1 = nm1;

        float rs0 = 0.f, rs1 = 0.f;
        unsigned pH0[8], pH1[8], pL0[8], pL1[8];
#pragma unroll
        for (int nf = 0; nf < 8; nf++) {
            float p00 = fast_exp(sc[nf][0] - nm0);
            float p01 = fast_exp(sc[nf][1] - nm0);
            float p10 = fast_exp(sc[nf][2] - nm1);
            float p11 = fast_exp(sc[nf][3] - nm1);
            rs0 += p00 + p01; rs1 += p10 + p11;
            __nv_bfloat16 h00 = __float2bfloat16(p00), h01 = __float2bfloat16(p01);
            __nv_bfloat16 h10 = __float2bfloat16(p10), h11 = __float2bfloat16(p11);
            pH0[nf] = pack_bf2(h00, h01);
            pH1[nf] = pack_bf2(h10, h11);
            pL0[nf] = pack_bf2(__float2bfloat16(p00 - __bfloat162float(h00)),
                               __float2bfloat16(p01 - __bfloat162float(h01)));
            pL1[nf] = pack_bf2(__float2bfloat16(p10 - __bfloat162float(h10)),
                               __float2bfloat16(p11 - __bfloat162float(h11)));
        }
        rs0 += __shfl_xor_sync(0xffffffffu, rs0, 1);
        rs0 += __shfl_xor_sync(0xffffffffu, rs0, 2);
        rs1 += __shfl_xor_sync(0xffffffffu, rs1, 1);
        rs1 += __shfl_xor_sync(0xffffffffu, rs1, 2);
        l0 = l0 * al0 + rs0; l1 = l1 * al1 + rs1;
#pragma unroll
        for (int nf = 0; nf < 8; nf++) {
            z[nf][0] *= al0; z[nf][1] *= al0; z[nf][2] *= al1; z[nf][3] *= al1;
        }

        // z += P V (3 passes)
#pragma unroll
        for (int c = 0; c < 4; c++) {
            unsigned aH[4] = {pH0[2 * c], pH1[2 * c], pH0[2 * c + 1], pH1[2 * c + 1]};
            unsigned aL[4] = {pL0[2 * c], pL1[2 * c], pL0[2 * c + 1], pL1[2 * c + 1]};
#pragma unroll
            for (int nf = 0; nf < 8; nf++) {
                unsigned bh[2], bl[2];
                ldsm_x2t(sVh + (c * 16 + a_r) * A_STRB + nf * 16, bh[0], bh[1]);
                ldsm_x2t(sVl + (c * 16 + a_r) * A_STRB + nf * 16, bl[0], bl[1]);
                mma_bf16(z[nf], aH, bh);
                mma_bf16(z[nf], aH, bl);
                mma_bf16(z[nf], aL, bh);
            }
        }
        __syncthreads();
    }

    // epilogue
    float i0 = 1.f / l0, i1 = 1.f / l1;
    size_t t0 = tok0 + wid * 16 + grp;
#pragma unroll
    for (int nf = 0; nf < 8; nf++) {
        int d = hq + nf * 8 + tig * 2;
        __nv_bfloat16 hA, lA, hB, lB;
        __nv_bfloat162 ph, pl;
        split2(z[nf][0] * i0, hA, lA); split2(z[nf][1] * i0, hB, lB);
        ph.x = hA; ph.y = hB; pl.x = lA; pl.y = lB;
        *(__nv_bfloat162*)&g_zhi[t0 * KDIM + d] = ph;
        *(__nv_bfloat162*)&g_zlo[t0 * KDIM + d] = pl;
        split2(z[nf][2] * i1, hA, lA); split2(z[nf][3] * i1, hB, lB);
        ph.x = hA; ph.y = hB; pl.x = lA; pl.y = lB;
        *(__nv_bfloat162*)&g_zhi[(t0 + 8) * KDIM + d] = ph;
        *(__nv_bfloat162*)&g_zlo[(t0 + 8) * KDIM + d] = pl;
    }
}

// ---------------- launch -----------------------------------------------------
extern "C" void kernel_launch(void* const* d_in, const int* in_sizes, int n_in,
                              void* d_out, int out_size) {
    const float* x  = (const float*)d_in[0];
    const float* WQ = (const float*)d_in[1];
    const float* WK = (const float*)d_in[2];
    const float* WV = (const float*)d_in[3];
    const float* bQ = (const float*)d_in[4];
    const float* bK = (const float*)d_in[5];
    const float* bV = (const float*)d_in[6];
    const float* WO = (const float*)d_in[7];
    const float* bO = (const float*)d_in[8];
    float* out = (float*)d_out;

    __nv_bfloat16 *pxhi, *pxlo, *pWthi, *pWtlo, *pWohi, *pWolo, *pqh, *pql, *pzhi, *pzlo;
    float* pbqkv;
    cudaGetSymbolAddress((void**)&pxhi,  g_xhi);
    cudaGetSymbolAddress((void**)&pxlo,  g_xlo);
    cudaGetSymbolAddress((void**)&pWthi, g_Wthi);
    cudaGetSymbolAddress((void**)&pWtlo, g_Wtlo);
    cudaGetSymbolAddress((void**)&pWohi, g_Wohi);
    cudaGetSymbolAddress((void**)&pWolo, g_Wolo);
    cudaGetSymbolAddress((void**)&pqh,   g_qkvhi);
    cudaGetSymbolAddress((void**)&pql,   g_qkvlo);
    cudaGetSymbolAddress((void**)&pzhi,  g_zhi);
    cudaGetSymbolAddress((void**)&pzlo,  g_zlo);
    cudaGetSymbolAddress((void**)&pbqkv, g_bqkv);

    cudaFuncSetAttribute(gemm_hmma<true>,  cudaFuncAttributeMaxDynamicSharedMemorySize, GSMEM);
    cudaFuncSetAttribute(gemm_hmma<false>, cudaFuncAttributeMaxDynamicSharedMemorySize, GSMEM);
    cudaFuncSetAttribute(attn_hmma, cudaFuncAttributeMaxDynamicSharedMemorySize, A_SMEM);

    // 1) weight repack + x split
    prep_weights<<<(DMODEL * DMODEL + 255) / 256, 256>>>(WQ, WK, WV, bQ, bK, bV, WO);
    convert_split<<<(MTOK * KDIM + 255) / 256, 256>>>(x, pxhi, pxlo, MTOK * KDIM);

    // 2) QKV projection -> bf16 hi/lo qkv
    gemm_hmma<true><<<dim3(NQKV / 128, MTOK / 128), 256, GSMEM>>>(
        pxhi, pxlo, pWthi, pWtlo, pbqkv, nullptr, pqh, pql, NQKV);

    // 3) tensor-core causal flash attention -> bf16 hi/lo z
    attn_hmma<<<dim3(SEQ / 128, HEADS, BATCH), 256, A_SMEM>>>(pqh, pql);

    // 4) output projection (fp32 out)
    gemm_hmma<false><<<dim3(DMODEL / 128, MTOK / 128), 256, GSMEM>>>(
        pzhi, pzlo, pWohi, pWolo, bO, out, nullptr, nullptr, DMODEL);
}